// round 12
// baseline (speedup 1.0000x reference)
#include <cuda_runtime.h>
#include <cstdint>

// Residual quantizer, fp32, arithmetic mirror of the reference
// (validated rel_err 7.351969e-4, all FMA chains bitwise-preserved).
// Round 12: round-6 engine (PPT=2, 32-code tiles: best mix-cap 70%) pushed
// to 10 warps/SM:
//  * C streamed in two 128-code halves (32 KB) -> R 160K + C 32K = 197.6 KB
//    fits TPB=320 in one block (10 warps; round 6 was 8).
//  * per-j code loads split into two batches of 16 codes with FMAs between:
//    live code regs halved -> demand ~160 under the 204-reg cap of
//    launch_bounds(320,1) (round 8 spilled because demand was ~254).
//  * unroll 4 (not 8) to limit ptxas hoisting pressure.
//  * residual update gathers chosen codes from gmem (bitwise-same values;
//    half-0 C is overwritten by half 1) - validated round 11.

#define KCODES 256
#define DIM 64
#define LEVELS 4
#define TPB 320
#define PPT 2
#define NPTS (TPB * PPT)         // 640 points per block
#define RST NPTS                 // R row stride (floats) = 640
#define KHALF 128                // codes per staged half
#define CST KHALF                // C row stride (floats), 512 B rows
#define R_BYTES (DIM * RST * 4)              // 163840
#define C_BYTES (DIM * CST * 4)              // 32768
#define SMEM_BYTES (R_BYTES + C_BYTES + KCODES * 4)   // 197632

#define FMA2(d, a, b, c) \
    asm("fma.rn.f32x2 %0, %1, %2, %3;" : "=l"(d) : "l"(a), "l"(b), "l"(c))
#define DUP2(d, s) asm("mov.b64 %0, {%1, %1};" : "=l"(d) : "f"(s))
#define LDS_V2U64(a, b, addr) \
    asm("ld.shared.v2.u64 {%0,%1}, [%2];" : "=l"(a), "=l"(b) : "r"(addr))

__global__ void __launch_bounds__(TPB, 1)
rq_kernel(const float* __restrict__ z, const float* __restrict__ cb,
          float* __restrict__ out, int B) {
    extern __shared__ __align__(16) char sm_raw[];
    float* R  = reinterpret_cast<float*>(sm_raw);
    float* C  = reinterpret_cast<float*>(sm_raw + R_BYTES);
    float* c2 = reinterpret_cast<float*>(sm_raw + R_BYTES + C_BYTES);

    const int tid = threadIdx.x;
    const int lp0 = 2 * tid;
    const long p0_raw = (long)blockIdx.x * NPTS + lp0;
    const long p0 = p0_raw < B ? p0_raw : (B - 1);
    const long p1 = (p0_raw + 1) < B ? (p0_raw + 1) : (B - 1);

    // ---- init residual R[j][lp0..lp0+1] = z ----
    {
        const float4* z0 = reinterpret_cast<const float4*>(z + p0 * DIM);
        const float4* z1 = reinterpret_cast<const float4*>(z + p1 * DIM);
#pragma unroll
        for (int i = 0; i < 16; i++) {
            float4 a = z0[i], b = z1[i];
            *reinterpret_cast<float2*>(R + (4 * i + 0) * RST + lp0) =
                make_float2(a.x, b.x);
            *reinterpret_cast<float2*>(R + (4 * i + 1) * RST + lp0) =
                make_float2(a.y, b.y);
            *reinterpret_cast<float2*>(R + (4 * i + 2) * RST + lp0) =
                make_float2(a.z, b.z);
            *reinterpret_cast<float2*>(R + (4 * i + 3) * RST + lp0) =
                make_float2(a.w, b.w);
        }
    }

    const unsigned smR = (unsigned)__cvta_generic_to_shared(R) + lp0 * 4;
    const unsigned smC = (unsigned)__cvta_generic_to_shared(C);

    int id0[LEVELS], id1[LEVELS];

#pragma unroll 1
    for (int lvl = 0; lvl < LEVELS; lvl++) {
        float r2a, r2b;
        float best0, best1;
        int bi0, bi1;

#pragma unroll 1
        for (int half = 0; half < 2; half++) {
            __syncthreads();   // everyone done reading prev C contents
            // ---- stage half: C[j][k] = cb[lvl][half*128+k][j], k<128 ----
            if (tid < KHALF) {
                const int gk = half * KHALF + tid;
                const float4* src = reinterpret_cast<const float4*>(
                    cb + ((size_t)lvl * KCODES + gk) * DIM);
#pragma unroll
                for (int i = 0; i < 16; i++) {
                    float4 v = src[i];
                    C[(4 * i + 0) * CST + tid] = v.x;
                    C[(4 * i + 1) * CST + tid] = v.y;
                    C[(4 * i + 2) * CST + tid] = v.z;
                    C[(4 * i + 3) * CST + tid] = v.w;
                }
                // c2: square-then-add, sequential over dims
                float s = 0.f;
#pragma unroll
                for (int j = 0; j < DIM; j++) {
                    float c = C[j * CST + tid];
                    s = __fadd_rn(s, __fmul_rn(c, c));
                }
                c2[gk] = s;
            }
            __syncthreads();

            if (half == 0) {
                // ---- r2 for my 2 points (sequential chains) ----
                r2a = 0.f; r2b = 0.f;
#pragma unroll
                for (int j = 0; j < DIM; j++) {
                    float2 rv =
                        *reinterpret_cast<const float2*>(R + j * RST + lp0);
                    r2a = __fadd_rn(r2a, __fmul_rn(rv.x, rv.x));
                    r2b = __fadd_rn(r2b, __fmul_rn(rv.y, rv.y));
                }
                best0 = __int_as_float(0x7F800000);
                best1 = __int_as_float(0x7F800000);
                bi0 = 0; bi1 = 0;
            }

            // ---- distance pass: 4 tiles of 32 codes per half ----
#pragma unroll 1
            for (int kt = 0; kt < 4; kt++) {
                const unsigned cA = smC + kt * 128;   // 32 codes * 4 B
                unsigned long long a0[16], a1[16];
#pragma unroll
                for (int m = 0; m < 16; m++) { a0[m] = 0ULL; a1[m] = 0ULL; }

#pragma unroll 4
                for (int j = 0; j < DIM; j++) {
                    float rx, ry;
                    asm("ld.shared.v2.f32 {%0,%1}, [%2];"
                        : "=f"(rx), "=f"(ry) : "r"(smR + j * (RST * 4)));
                    unsigned long long ra, rb;
                    DUP2(ra, rx); DUP2(rb, ry);
                    const unsigned ca = cA + j * (CST * 4);
                    // batch 1: codes 0..15 of the tile
                    {
                        unsigned long long c[8];
                        LDS_V2U64(c[0], c[1], ca);
                        LDS_V2U64(c[2], c[3], ca + 16);
                        LDS_V2U64(c[4], c[5], ca + 32);
                        LDS_V2U64(c[6], c[7], ca + 48);
#pragma unroll
                        for (int m = 0; m < 8; m++) {
                            FMA2(a0[m], ra, c[m], a0[m]);
                            FMA2(a1[m], rb, c[m], a1[m]);
                        }
                    }
                    // batch 2: codes 16..31 of the tile
                    {
                        unsigned long long c[8];
                        LDS_V2U64(c[0], c[1], ca + 64);
                        LDS_V2U64(c[2], c[3], ca + 80);
                        LDS_V2U64(c[4], c[5], ca + 96);
                        LDS_V2U64(c[6], c[7], ca + 112);
#pragma unroll
                        for (int m = 0; m < 8; m++) {
                            FMA2(a0[8 + m], ra, c[m], a0[8 + m]);
                            FMA2(a1[8 + m], rb, c[m], a1[8 + m]);
                        }
                    }
                }
                // ---- distances + argmin (ascending k, strict <) ----
#pragma unroll
                for (int m = 0; m < 16; m++) {
                    const int k0 = half * KHALF + kt * 32 + 2 * m;
                    const float cc0 = c2[k0], cc1 = c2[k0 + 1];
                    float lo, hi;
                    asm("mov.b64 {%0,%1}, %2;"
                        : "=f"(lo), "=f"(hi) : "l"(a0[m]));
                    float d0 = __fadd_rn(
                        __fsub_rn(r2a, __fmul_rn(2.0f, lo)), cc0);
                    float d1 = __fadd_rn(
                        __fsub_rn(r2a, __fmul_rn(2.0f, hi)), cc1);
                    if (d0 < best0) { best0 = d0; bi0 = k0; }
                    if (d1 < best0) { best0 = d1; bi0 = k0 + 1; }
                    asm("mov.b64 {%0,%1}, %2;"
                        : "=f"(lo), "=f"(hi) : "l"(a1[m]));
                    float e0 = __fadd_rn(
                        __fsub_rn(r2b, __fmul_rn(2.0f, lo)), cc0);
                    float e1 = __fadd_rn(
                        __fsub_rn(r2b, __fmul_rn(2.0f, hi)), cc1);
                    if (e0 < best1) { best1 = e0; bi1 = k0; }
                    if (e1 < best1) { best1 = e1; bi1 = k0 + 1; }
                }
            }
        }
        id0[lvl] = bi0; id1[lvl] = bi1;

        // ---- residual update: gather chosen codes from GMEM (bitwise-same
        // values as the smem copy; half-0 C was overwritten by half 1) ----
        {
            const float4* cp0 = reinterpret_cast<const float4*>(
                cb + ((size_t)lvl * KCODES + bi0) * DIM);
            const float4* cp1 = reinterpret_cast<const float4*>(
                cb + ((size_t)lvl * KCODES + bi1) * DIM);
#pragma unroll
            for (int cch = 0; cch < 16; cch++) {
                float4 v0 = __ldg(cp0 + cch);
                float4 v1 = __ldg(cp1 + cch);
                float cu[4][2] = {{v0.x, v1.x}, {v0.y, v1.y},
                                  {v0.z, v1.z}, {v0.w, v1.w}};
#pragma unroll
                for (int u = 0; u < 4; u++) {
                    const int j = 4 * cch + u;
                    float2 rv =
                        *reinterpret_cast<const float2*>(R + j * RST + lp0);
                    rv.x = __fsub_rn(rv.x, cu[u][0]);
                    rv.y = __fsub_rn(rv.y, cu[u][1]);
                    *reinterpret_cast<float2*>(R + j * RST + lp0) = rv;
                }
            }
        }
    }

    // ---- epilogue (chunk-wise; validated bitwise vs reference) ----
    const long pts[2] = {p0, p1};
    const bool valid[2] = {p0_raw < B, (p0_raw + 1) < B};
#pragma unroll 1
    for (int s = 0; s < 2; s++) {
        if (!valid[s]) continue;
        const long p = pts[s];
        const int* ids = (s == 0) ? id0 : id1;
        const float4* cp0 = reinterpret_cast<const float4*>(
            cb + ((size_t)0 * KCODES + ids[0]) * DIM);
        const float4* cp1 = reinterpret_cast<const float4*>(
            cb + ((size_t)1 * KCODES + ids[1]) * DIM);
        const float4* cp2 = reinterpret_cast<const float4*>(
            cb + ((size_t)2 * KCODES + ids[2]) * DIM);
        const float4* cp3 = reinterpret_cast<const float4*>(
            cb + ((size_t)3 * KCODES + ids[3]) * DIM);
        const float4* zp = reinterpret_cast<const float4*>(z + p * DIM);
        float4* qst = reinterpret_cast<float4*>(out + (size_t)p * DIM);
        float4* qq  = reinterpret_cast<float4*>(out + (size_t)B * (DIM + 4) +
                                                (size_t)p * DIM);
#pragma unroll
        for (int i = 0; i < 16; i++) {
            float4 v0 = __ldg(cp0 + i), v1 = __ldg(cp1 + i);
            float4 v2 = __ldg(cp2 + i), v3 = __ldg(cp3 + i);
            // quantized = ((q0 + q1) + q2) + q3, sequential (matches ref)
            float4 qv;
            qv.x = __fadd_rn(__fadd_rn(__fadd_rn(v0.x, v1.x), v2.x), v3.x);
            qv.y = __fadd_rn(__fadd_rn(__fadd_rn(v0.y, v1.y), v2.y), v3.y);
            qv.z = __fadd_rn(__fadd_rn(__fadd_rn(v0.z, v1.z), v2.z), v3.z);
            qv.w = __fadd_rn(__fadd_rn(__fadd_rn(v0.w, v1.w), v2.w), v3.w);
            float4 zv = zp[i];
            float4 sv;
            sv.x = __fadd_rn(zv.x, __fsub_rn(qv.x, zv.x));
            sv.y = __fadd_rn(zv.y, __fsub_rn(qv.y, zv.y));
            sv.z = __fadd_rn(zv.z, __fsub_rn(qv.z, zv.z));
            sv.w = __fadd_rn(zv.w, __fsub_rn(qv.w, zv.w));
            qst[i] = sv;
            qq[i] = qv;
        }
        float4 iv;
        iv.x = (float)ids[0]; iv.y = (float)ids[1];
        iv.z = (float)ids[2]; iv.w = (float)ids[3];
        reinterpret_cast<float4*>(out + (size_t)B * DIM)[p] = iv;
    }
}

extern "C" void kernel_launch(void* const* d_in, const int* in_sizes, int n_in,
                              void* d_out, int out_size) {
    const float* z = (const float*)d_in[0];
    const float* cb = (const float*)d_in[1];
    float* out = (float*)d_out;
    int B = in_sizes[0] / DIM;

    cudaFuncSetAttribute(rq_kernel, cudaFuncAttributeMaxDynamicSharedMemorySize,
                         SMEM_BYTES);
    int blocks = (B + NPTS - 1) / NPTS;
    rq_kernel<<<blocks, TPB, SMEM_BYTES>>>(z, cb, out, B);
}

// round 13
// speedup vs baseline: 1.2764x; 1.2764x over previous
#include <cuda_runtime.h>
#include <cstdint>

// Residual quantizer, fp32, arithmetic mirror of the reference
// (validated rel_err 7.351969e-4, all FMA chains bitwise-preserved).
// Round 13: round-4 engine (PPT=2, 16-code tiles, full C staged once per
// level, measured regs=214, per-warp fma 6.8%) scaled 8 -> 9 warps:
//   TPB=288, NPTS=576: R 144K + C 65K + c2 = 215K <= 227K opt-in.
//   Reg cap at 288 thr = 224 >= 214 demand -> NO SPILL by construction
//   (the 32-code engine needs 254 regs and cannot scale past TPB=256;
//   streaming C in halves was tried thrice and always lost to one-shot
//   staging). Single stage pass, one sync pair per level.

#define KCODES 256
#define DIM 64
#define LEVELS 4
#define TPB 288
#define NPTS (TPB * 2)           // 576 points per block
#define RST NPTS                 // R row stride (floats) = 576
#define CST 260                  // C row stride (floats), 1040 B rows
#define R_BYTES (DIM * RST * 4)              // 147456
#define C_BYTES (DIM * CST * 4)              // 66560
#define SMEM_BYTES (R_BYTES + C_BYTES + KCODES * 4)   // 215040

#define FMA2(d, a, b, c) \
    asm("fma.rn.f32x2 %0, %1, %2, %3;" : "=l"(d) : "l"(a), "l"(b), "l"(c))
#define DUP2(d, s) asm("mov.b64 %0, {%1, %1};" : "=l"(d) : "f"(s))
#define LDS_V2U64(a, b, addr) \
    asm("ld.shared.v2.u64 {%0,%1}, [%2];" : "=l"(a), "=l"(b) : "r"(addr))

__global__ void __launch_bounds__(TPB, 1)
rq_kernel(const float* __restrict__ z, const float* __restrict__ cb,
          float* __restrict__ out, int B) {
    extern __shared__ __align__(16) char sm_raw[];
    float* R  = reinterpret_cast<float*>(sm_raw);
    float* C  = reinterpret_cast<float*>(sm_raw + R_BYTES);
    float* c2 = reinterpret_cast<float*>(sm_raw + R_BYTES + C_BYTES);

    const int tid = threadIdx.x;
    const int lp0 = 2 * tid;
    const long p0_raw = (long)blockIdx.x * NPTS + lp0;
    const long p0 = p0_raw < B ? p0_raw : (B - 1);
    const long p1 = (p0_raw + 1) < B ? (p0_raw + 1) : (B - 1);

    // ---- init residual R[j][lp0..lp0+1] = z ----
    {
        const float4* z0 = reinterpret_cast<const float4*>(z + p0 * DIM);
        const float4* z1 = reinterpret_cast<const float4*>(z + p1 * DIM);
#pragma unroll
        for (int i = 0; i < 16; i++) {
            float4 a = z0[i], b = z1[i];
            *reinterpret_cast<float2*>(R + (4 * i + 0) * RST + lp0) =
                make_float2(a.x, b.x);
            *reinterpret_cast<float2*>(R + (4 * i + 1) * RST + lp0) =
                make_float2(a.y, b.y);
            *reinterpret_cast<float2*>(R + (4 * i + 2) * RST + lp0) =
                make_float2(a.z, b.z);
            *reinterpret_cast<float2*>(R + (4 * i + 3) * RST + lp0) =
                make_float2(a.w, b.w);
        }
    }

    const unsigned smR = (unsigned)__cvta_generic_to_shared(R) + lp0 * 4;
    const unsigned smC = (unsigned)__cvta_generic_to_shared(C);

    int id0[LEVELS], id1[LEVELS];

#pragma unroll 1
    for (int lvl = 0; lvl < LEVELS; lvl++) {
        __syncthreads();   // prev level's residual update read C
        // ---- stage codebook level transposed: C[j][k] = cb[lvl][k][j] ----
        if (tid < KCODES) {
            const float4* src = reinterpret_cast<const float4*>(
                cb + ((size_t)lvl * KCODES + tid) * DIM);
#pragma unroll
            for (int i = 0; i < 16; i++) {
                float4 v = src[i];
                C[(4 * i + 0) * CST + tid] = v.x;
                C[(4 * i + 1) * CST + tid] = v.y;
                C[(4 * i + 2) * CST + tid] = v.z;
                C[(4 * i + 3) * CST + tid] = v.w;
            }
        }
        __syncthreads();
        // ---- c2[k]: square-then-add, sequential over dims ----
        if (tid < KCODES) {
            float s = 0.f;
#pragma unroll
            for (int j = 0; j < DIM; j++) {
                float c = C[j * CST + tid];
                s = __fadd_rn(s, __fmul_rn(c, c));
            }
            c2[tid] = s;
        }
        __syncthreads();

        // ---- r2 for my 2 points (sequential chains) ----
        float r2a = 0.f, r2b = 0.f;
#pragma unroll
        for (int j = 0; j < DIM; j++) {
            float2 rv = *reinterpret_cast<const float2*>(R + j * RST + lp0);
            r2a = __fadd_rn(r2a, __fmul_rn(rv.x, rv.x));
            r2b = __fadd_rn(r2b, __fmul_rn(rv.y, rv.y));
        }

        float best0 = __int_as_float(0x7F800000);
        float best1 = __int_as_float(0x7F800000);
        int bi0 = 0, bi1 = 0;

        // ---- distance pass: 16 tiles of 16 codes, warp-uniform code loads
#pragma unroll 1
        for (int kt = 0; kt < 16; kt++) {
            const unsigned cA = smC + kt * 64;   // 16 codes * 4 B
            unsigned long long a0[8], a1[8];
#pragma unroll
            for (int m = 0; m < 8; m++) { a0[m] = 0ULL; a1[m] = 0ULL; }

#pragma unroll 8
            for (int j = 0; j < DIM; j++) {
                float rx, ry;
                asm("ld.shared.v2.f32 {%0,%1}, [%2];"
                    : "=f"(rx), "=f"(ry) : "r"(smR + j * (RST * 4)));
                unsigned long long ra, rb;
                DUP2(ra, rx); DUP2(rb, ry);
                unsigned long long c[8];
                const unsigned ca = cA + j * (CST * 4);
                LDS_V2U64(c[0], c[1], ca);
                LDS_V2U64(c[2], c[3], ca + 16);
                LDS_V2U64(c[4], c[5], ca + 32);
                LDS_V2U64(c[6], c[7], ca + 48);
#pragma unroll
                for (int m = 0; m < 8; m++) FMA2(a0[m], ra, c[m], a0[m]);
#pragma unroll
                for (int m = 0; m < 8; m++) FMA2(a1[m], rb, c[m], a1[m]);
            }
            // ---- distances + argmin (ascending k, strict < => first-min)
#pragma unroll
            for (int m = 0; m < 8; m++) {
                const int k0 = kt * 16 + 2 * m;
                const float cc0 = c2[k0], cc1 = c2[k0 + 1];
                float lo, hi;
                asm("mov.b64 {%0,%1}, %2;" : "=f"(lo), "=f"(hi) : "l"(a0[m]));
                float d0 = __fadd_rn(__fsub_rn(r2a, __fmul_rn(2.0f, lo)), cc0);
                float d1 = __fadd_rn(__fsub_rn(r2a, __fmul_rn(2.0f, hi)), cc1);
                if (d0 < best0) { best0 = d0; bi0 = k0; }
                if (d1 < best0) { best0 = d1; bi0 = k0 + 1; }
                asm("mov.b64 {%0,%1}, %2;" : "=f"(lo), "=f"(hi) : "l"(a1[m]));
                float e0 = __fadd_rn(__fsub_rn(r2b, __fmul_rn(2.0f, lo)), cc0);
                float e1 = __fadd_rn(__fsub_rn(r2b, __fmul_rn(2.0f, hi)), cc1);
                if (e0 < best1) { best1 = e0; bi1 = k0; }
                if (e1 < best1) { best1 = e1; bi1 = k0 + 1; }
            }
        }
        id0[lvl] = bi0; id1[lvl] = bi1;

        // ---- residual update for my own points (reads C; sync at loop top)
#pragma unroll
        for (int j = 0; j < DIM; j++) {
            float2 rv = *reinterpret_cast<const float2*>(R + j * RST + lp0);
            rv.x = __fsub_rn(rv.x, C[j * CST + bi0]);
            rv.y = __fsub_rn(rv.y, C[j * CST + bi1]);
            *reinterpret_cast<float2*>(R + j * RST + lp0) = rv;
        }
    }

    // ---- epilogue (chunk-wise; validated bitwise vs reference) ----
    const long pts[2] = {p0, p1};
    const bool valid[2] = {p0_raw < B, (p0_raw + 1) < B};
#pragma unroll 1
    for (int s = 0; s < 2; s++) {
        if (!valid[s]) continue;
        const long p = pts[s];
        const int* ids = (s == 0) ? id0 : id1;
        const float4* cp0 = reinterpret_cast<const float4*>(
            cb + ((size_t)0 * KCODES + ids[0]) * DIM);
        const float4* cp1 = reinterpret_cast<const float4*>(
            cb + ((size_t)1 * KCODES + ids[1]) * DIM);
        const float4* cp2 = reinterpret_cast<const float4*>(
            cb + ((size_t)2 * KCODES + ids[2]) * DIM);
        const float4* cp3 = reinterpret_cast<const float4*>(
            cb + ((size_t)3 * KCODES + ids[3]) * DIM);
        const float4* zp = reinterpret_cast<const float4*>(z + p * DIM);
        float4* qst = reinterpret_cast<float4*>(out + (size_t)p * DIM);
        float4* qq  = reinterpret_cast<float4*>(out + (size_t)B * (DIM + 4) +
                                                (size_t)p * DIM);
#pragma unroll
        for (int i = 0; i < 16; i++) {
            float4 v0 = __ldg(cp0 + i), v1 = __ldg(cp1 + i);
            float4 v2 = __ldg(cp2 + i), v3 = __ldg(cp3 + i);
            // quantized = ((q0 + q1) + q2) + q3, sequential (matches ref)
            float4 qv;
            qv.x = __fadd_rn(__fadd_rn(__fadd_rn(v0.x, v1.x), v2.x), v3.x);
            qv.y = __fadd_rn(__fadd_rn(__fadd_rn(v0.y, v1.y), v2.y), v3.y);
            qv.z = __fadd_rn(__fadd_rn(__fadd_rn(v0.z, v1.z), v2.z), v3.z);
            qv.w = __fadd_rn(__fadd_rn(__fadd_rn(v0.w, v1.w), v2.w), v3.w);
            float4 zv = zp[i];
            float4 sv;
            sv.x = __fadd_rn(zv.x, __fsub_rn(qv.x, zv.x));
            sv.y = __fadd_rn(zv.y, __fsub_rn(qv.y, zv.y));
            sv.z = __fadd_rn(zv.z, __fsub_rn(qv.z, zv.z));
            sv.w = __fadd_rn(zv.w, __fsub_rn(qv.w, zv.w));
            qst[i] = sv;
            qq[i] = qv;
        }
        float4 iv;
        iv.x = (float)ids[0]; iv.y = (float)ids[1];
        iv.z = (float)ids[2]; iv.w = (float)ids[3];
        reinterpret_cast<float4*>(out + (size_t)B * DIM)[p] = iv;
    }
}

extern "C" void kernel_launch(void* const* d_in, const int* in_sizes, int n_in,
                              void* d_out, int out_size) {
    const float* z = (const float*)d_in[0];
    const float* cb = (const float*)d_in[1];
    float* out = (float*)d_out;
    int B = in_sizes[0] / DIM;

    cudaFuncSetAttribute(rq_kernel, cudaFuncAttributeMaxDynamicSharedMemorySize,
                         SMEM_BYTES);
    int blocks = (B + NPTS - 1) / NPTS;
    rq_kernel<<<blocks, TPB, SMEM_BYTES>>>(z, cb, out, B);
}